// round 3
// baseline (speedup 1.0000x reference)
#include <cuda_runtime.h>
#include <cstdint>
#include <cstddef>

#define BATCH 4
#define CH    256
#define QVCH  512
#define NPIX  9216   // 96*96
#define MPIX  256    // 16*16
#define HEADS 4
#define DHEAD 64
#define NBH   (BATCH*HEADS)
#define KCHUNKS 16
#define ROWS_PER_CHUNK (NPIX/KCHUNKS)   // 576
#define IBLKS (NPIX/128)                // 72 logits i-blocks per bh
#define SCALE 0.125f

// ---------------- scratch (device globals; allocation-free) ----------------
__device__ float g_fqv[BATCH*QVCH*NPIX];
__device__ float g_mqv[BATCH*QVCH*MPIX];
__device__ float g_logits[(size_t)NBH*NPIX*MPIX];
__device__ float g_feato[BATCH*CH*NPIX];
__device__ float g_mapo[BATCH*CH*MPIX];
__device__ float g_mapo_part[KCHUNKS*BATCH*CH*MPIX];
__device__ float g_pm[NBH*IBLKS*MPIX];
__device__ float g_ps[NBH*IBLKS*MPIX];
__device__ float g_cmax[NBH*MPIX];
__device__ float g_csum[NBH*MPIX];

// =================== 128x128 tiled 1x1-conv GEMM ===================
// Y[b][o][n] = sum_c W[o][c]*X[b][c][n]; grid (Npix/128, O/128, BATCH), block 256
__global__ void __launch_bounds__(256, 2)
conv1x1_big(const float* __restrict__ Wm, const float* __restrict__ X,
            float* __restrict__ Y, int C, int Npix, int O) {
    __shared__ float As[8][132];   // [c][o]
    __shared__ float Bs[8][128];   // [c][n]
    int b = blockIdx.z;
    const float* Xb = X + (size_t)b * C * Npix;
    float* Yb = Y + (size_t)b * O * Npix;
    int o0 = blockIdx.y * 128, n0 = blockIdx.x * 128;
    int tid = threadIdx.x;
    int tx = tid & 15, ty = tid >> 4;

    // load mappings
    int oA = tid >> 1, cqA = (tid & 1) << 2;
    int cB = tid >> 5, nB = (tid & 31) << 2;
    const float* Wp = Wm + (size_t)(o0 + oA) * C + cqA;
    const float* Xp = Xb + (size_t)cB * Npix + n0 + nB;

    float acc[8][8] = {};
    float4 aw = *(const float4*)Wp;
    float4 bw = *(const float4*)Xp;

    for (int k0 = 0; k0 < C; k0 += 8) {
        As[cqA + 0][oA] = aw.x;
        As[cqA + 1][oA] = aw.y;
        As[cqA + 2][oA] = aw.z;
        As[cqA + 3][oA] = aw.w;
        *(float4*)&Bs[cB][nB] = bw;
        __syncthreads();
        if (k0 + 8 < C) {
            aw = *(const float4*)(Wp + k0 + 8);
            bw = *(const float4*)(Xp + (size_t)(k0 + 8) * Npix);
        }
        #pragma unroll
        for (int k = 0; k < 8; k++) {
            float a[8], bb[8];
            #pragma unroll
            for (int r = 0; r < 8; r++) a[r] = As[k][ty * 8 + r];
            #pragma unroll
            for (int c = 0; c < 8; c++) bb[c] = Bs[k][tx * 8 + c];
            #pragma unroll
            for (int r = 0; r < 8; r++)
                #pragma unroll
                for (int c = 0; c < 8; c++) acc[r][c] += a[r] * bb[c];
        }
        __syncthreads();
    }
    #pragma unroll
    for (int r = 0; r < 8; r++) {
        float* yrow = Yb + (size_t)(o0 + ty * 8 + r) * Npix + n0 + tx * 8;
        float4 v0 = make_float4(acc[r][0], acc[r][1], acc[r][2], acc[r][3]);
        float4 v1 = make_float4(acc[r][4], acc[r][5], acc[r][6], acc[r][7]);
        *(float4*)yrow = v0;
        *(float4*)(yrow + 4) = v1;
    }
}

// =================== small 64x64 conv (MPIX side) ===================
__global__ void conv1x1_small(const float* __restrict__ Wm,
                              const float* __restrict__ X,
                              float* __restrict__ Y,
                              int C, int Npix, int O) {
    __shared__ float As[16][65];
    __shared__ float Bs[16][64];
    int b = blockIdx.z;
    const float* Xb = X + (size_t)b * C * Npix;
    float* Yb = Y + (size_t)b * O * Npix;
    int o0 = blockIdx.y * 64, n0 = blockIdx.x * 64;
    int tid = threadIdx.x;
    int tx = tid & 15, ty = tid >> 4;
    float acc[4][4] = {};
    for (int k0 = 0; k0 < C; k0 += 16) {
        #pragma unroll
        for (int r = 0; r < 4; r++) {
            int idx = tid + r * 256;
            int c = idx & 15, o = idx >> 4;
            As[c][o] = Wm[(size_t)(o0 + o) * C + k0 + c];
        }
        #pragma unroll
        for (int r = 0; r < 4; r++) {
            int idx = tid + r * 256;
            int n = idx & 63, c = idx >> 6;
            Bs[c][n] = Xb[(size_t)(k0 + c) * Npix + n0 + n];
        }
        __syncthreads();
        #pragma unroll
        for (int k = 0; k < 16; k++) {
            float a[4], bb[4];
            #pragma unroll
            for (int r = 0; r < 4; r++) a[r] = As[k][ty * 4 + r];
            #pragma unroll
            for (int c2 = 0; c2 < 4; c2++) bb[c2] = Bs[k][tx * 4 + c2];
            #pragma unroll
            for (int r = 0; r < 4; r++)
                #pragma unroll
                for (int c2 = 0; c2 < 4; c2++) acc[r][c2] += a[r] * bb[c2];
        }
        __syncthreads();
    }
    #pragma unroll
    for (int r = 0; r < 4; r++)
        #pragma unroll
        for (int c2 = 0; c2 < 4; c2++)
            Yb[(size_t)(o0 + ty * 4 + r) * Npix + n0 + tx * 4 + c2] = acc[r][c2];
}

// =================== logits 128x128 + fused column partial stats ===================
// logits[bh][i][j] = SCALE * sum_d q[d][i]*k[d][j]; also per-block col max/sumexp
// grid (MPIX/128=2, NPIX/128=72, NBH), block 256
__global__ void __launch_bounds__(256, 2)
logits_big(const float* __restrict__ fqv, const float* __restrict__ mqv,
           float* __restrict__ logits, float* __restrict__ pm, float* __restrict__ ps) {
    __shared__ float Qs[8][128];   // [d][i]
    __shared__ float Ks[8][128];   // [d][j]
    __shared__ float red[16][128];
    int bh = blockIdx.z; int b = bh >> 2, h = bh & 3;
    int i0 = blockIdx.y * 128, j0 = blockIdx.x * 128;
    const float* qb = fqv + (size_t)b * QVCH * NPIX;
    const float* kb = mqv + (size_t)b * QVCH * MPIX;
    int tid = threadIdx.x;
    int tx = tid & 15, ty = tid >> 4;

    int dL = tid >> 5, e4 = (tid & 31) << 2;
    const float* qp = qb + (size_t)((dL << 2) + h) * NPIX + i0 + e4;
    const float* kp = kb + (size_t)((dL << 2) + h) * MPIX + j0 + e4;

    float acc[8][8] = {};
    float4 qw = *(const float4*)qp;
    float4 kw = *(const float4*)kp;

    for (int k0 = 0; k0 < DHEAD; k0 += 8) {
        *(float4*)&Qs[dL][e4] = qw;
        *(float4*)&Ks[dL][e4] = kw;
        __syncthreads();
        if (k0 + 8 < DHEAD) {
            qw = *(const float4*)(qp + (size_t)((k0 + 8) << 2) * NPIX);
            kw = *(const float4*)(kp + (size_t)((k0 + 8) << 2) * MPIX);
        }
        #pragma unroll
        for (int k = 0; k < 8; k++) {
            float a[8], bb[8];
            #pragma unroll
            for (int r = 0; r < 8; r++) a[r] = Qs[k][ty * 8 + r];
            #pragma unroll
            for (int c = 0; c < 8; c++) bb[c] = Ks[k][tx * 8 + c];
            #pragma unroll
            for (int r = 0; r < 8; r++)
                #pragma unroll
                for (int c = 0; c < 8; c++) acc[r][c] += a[r] * bb[c];
        }
        __syncthreads();
    }
    // scale + write logits
    float* lb = logits + (size_t)bh * NPIX * MPIX;
    #pragma unroll
    for (int r = 0; r < 8; r++) {
        #pragma unroll
        for (int c = 0; c < 8; c++) acc[r][c] *= SCALE;
        float* row = lb + (size_t)(i0 + ty * 8 + r) * MPIX + j0 + tx * 8;
        *(float4*)row = make_float4(acc[r][0], acc[r][1], acc[r][2], acc[r][3]);
        *(float4*)(row + 4) = make_float4(acc[r][4], acc[r][5], acc[r][6], acc[r][7]);
    }
    // fused column stats over this block's 128 rows
    float mloc[8];
    #pragma unroll
    for (int c = 0; c < 8; c++) {
        float m = acc[0][c];
        #pragma unroll
        for (int r = 1; r < 8; r++) m = fmaxf(m, acc[r][c]);
        mloc[c] = m;
    }
    #pragma unroll
    for (int c = 0; c < 8; c++) red[ty][tx * 8 + c] = mloc[c];
    __syncthreads();
    for (int s = 8; s > 0; s >>= 1) {
        if (ty < s) {
            #pragma unroll
            for (int c = 0; c < 8; c++)
                red[ty][tx * 8 + c] = fmaxf(red[ty][tx * 8 + c], red[ty + s][tx * 8 + c]);
        }
        __syncthreads();
    }
    float mcol[8];
    #pragma unroll
    for (int c = 0; c < 8; c++) mcol[c] = red[0][tx * 8 + c];
    __syncthreads();
    float sl[8];
    #pragma unroll
    for (int c = 0; c < 8; c++) {
        float s = 0.f;
        #pragma unroll
        for (int r = 0; r < 8; r++) s += __expf(acc[r][c] - mcol[c]);
        sl[c] = s;
    }
    #pragma unroll
    for (int c = 0; c < 8; c++) red[ty][tx * 8 + c] = sl[c];
    __syncthreads();
    for (int s = 8; s > 0; s >>= 1) {
        if (ty < s) {
            #pragma unroll
            for (int c = 0; c < 8; c++)
                red[ty][tx * 8 + c] += red[ty + s][tx * 8 + c];
        }
        __syncthreads();
    }
    if (ty == 0) {
        size_t base = ((size_t)bh * IBLKS + blockIdx.y) * MPIX + j0;
        #pragma unroll
        for (int c = 0; c < 8; c++) {
            pm[base + tx * 8 + c] = mcol[c];
            ps[base + tx * 8 + c] = red[0][tx * 8 + c];
        }
    }
}

// combine 72 i-block partials into column max/sum
__global__ void colstats_combine72(const float* __restrict__ pm,
                                   const float* __restrict__ ps,
                                   float* __restrict__ cm, float* __restrict__ cs) {
    int bh = blockIdx.x, j = threadIdx.x;
    float m = -1e30f;
    for (int c = 0; c < IBLKS; c++)
        m = fmaxf(m, pm[((size_t)bh * IBLKS + c) * MPIX + j]);
    float s = 0.f;
    for (int c = 0; c < IBLKS; c++)
        s += ps[((size_t)bh * IBLKS + c) * MPIX + j] *
             __expf(pm[((size_t)bh * IBLKS + c) * MPIX + j] - m);
    cm[bh * MPIX + j] = m;
    cs[bh * MPIX + j] = s;
}

// =================== feat_o: row softmax fused with P @ V (64x64 GEMM tiles) ===================
// grid (NPIX/64=144, NBH), block 256, dyn smem = 64*257*4 + 64*65*4
__global__ void __launch_bounds__(256, 2)
feato_kernel(const float* __restrict__ logits, const float* __restrict__ mqv,
             float* __restrict__ feato) {
    extern __shared__ float sm[];
    float* P = sm;              // [64][257]
    float* Vs = sm + 64 * 257;  // [64][65], reused as output staging
    int bh = blockIdx.y; int b = bh >> 2, h = bh & 3;
    int i0 = blockIdx.x * 64;
    const float* lb = logits + (size_t)bh * NPIX * MPIX;
    const float* vb = mqv + (size_t)b * QVCH * MPIX + (size_t)CH * MPIX;
    int tid = threadIdx.x, lane = tid & 31, warp = tid >> 5;
    int tx = tid & 15, ty = tid >> 4;

    // phase 1: softmax 8 rows per warp into P
    #pragma unroll
    for (int rr = 0; rr < 8; rr++) {
        int il = warp * 8 + rr;
        const float* row = lb + (size_t)(i0 + il) * MPIX;
        float x[8];
        float m = -1e30f;
        #pragma unroll
        for (int jj = 0; jj < 8; jj++) { x[jj] = row[jj * 32 + lane]; m = fmaxf(m, x[jj]); }
        #pragma unroll
        for (int off = 16; off; off >>= 1) m = fmaxf(m, __shfl_xor_sync(0xffffffffu, m, off));
        float s = 0.f;
        #pragma unroll
        for (int jj = 0; jj < 8; jj++) { x[jj] = __expf(x[jj] - m); s += x[jj]; }
        #pragma unroll
        for (int off = 16; off; off >>= 1) s += __shfl_xor_sync(0xffffffffu, s, off);
        float inv = 1.f / s;
        #pragma unroll
        for (int jj = 0; jj < 8; jj++) P[il * 257 + jj * 32 + lane] = x[jj] * inv;
    }
    __syncthreads();

    // phase 2: GEMM 64(i) x 64(d), K=256 in 4 chunks of 64
    float acc[4][4] = {};
    for (int kc = 0; kc < 4; kc++) {
        #pragma unroll
        for (int r = 0; r < 16; r++) {
            int idx = tid + r * 256;
            int k = idx & 63, d = idx >> 6;
            Vs[k * 65 + d] = vb[(size_t)((d << 2) + h) * MPIX + kc * 64 + k];
        }
        __syncthreads();
        #pragma unroll 4
        for (int k = 0; k < 64; k++) {
            float a[4], bb[4];
            #pragma unroll
            for (int r = 0; r < 4; r++) a[r] = P[(ty * 4 + r) * 257 + kc * 64 + k];
            #pragma unroll
            for (int c = 0; c < 4; c++) bb[c] = Vs[k * 65 + tx * 4 + c];
            #pragma unroll
            for (int r = 0; r < 4; r++)
                #pragma unroll
                for (int c = 0; c < 4; c++) acc[r][c] += a[r] * bb[c];
        }
        __syncthreads();
    }
    // stage output [i][d] then coalesced store
    #pragma unroll
    for (int r = 0; r < 4; r++)
        #pragma unroll
        for (int c = 0; c < 4; c++)
            Vs[(ty * 4 + r) * 65 + tx * 4 + c] = acc[r][c];
    __syncthreads();
    float* fb = feato + (size_t)b * CH * NPIX;
    #pragma unroll
    for (int r = 0; r < 16; r++) {
        int idx = tid + r * 256;
        int i = idx & 63, d = idx >> 6;
        fb[(size_t)((d << 2) + h) * NPIX + i0 + i] = Vs[i * 65 + d];
    }
}

// =================== map_o split-K partials ===================
__global__ void mapo_kernel(const float* __restrict__ logits,
                            const float* __restrict__ fqv,
                            const float* __restrict__ cm,
                            const float* __restrict__ cs,
                            float* __restrict__ part) {
    __shared__ float Es[16][64];
    __shared__ float Fs[16][65];
    __shared__ float cms[64], css[64];
    int bh = blockIdx.z; int b = bh >> 2, h = bh & 3;
    int j0 = blockIdx.x * 64;
    int chunk = blockIdx.y;
    int ibeg = chunk * ROWS_PER_CHUNK;
    const float* lb = logits + (size_t)bh * NPIX * MPIX;
    const float* fvb = fqv + (size_t)b * QVCH * NPIX + (size_t)CH * NPIX;
    int tid = threadIdx.x, tx = tid & 15, ty = tid >> 4;
    if (tid < 64) {
        cms[tid] = cm[bh * MPIX + j0 + tid];
        css[tid] = cs[bh * MPIX + j0 + tid];
    }
    __syncthreads();
    float acc[4][4] = {};
    for (int k0 = 0; k0 < ROWS_PER_CHUNK; k0 += 16) {
        int ib = ibeg + k0;
        #pragma unroll
        for (int r = 0; r < 4; r++) {
            int idx = tid + r * 256;
            int j = idx & 63, il = idx >> 6;
            float x = lb[(size_t)(ib + il) * MPIX + j0 + j];
            Es[il][j] = __expf(x - cms[j]);
        }
        #pragma unroll
        for (int r = 0; r < 4; r++) {
            int idx = tid + r * 256;
            int il = idx & 15, d = idx >> 4;
            Fs[il][d] = fvb[(size_t)((d << 2) + h) * NPIX + ib + il];
        }
        __syncthreads();
        #pragma unroll
        for (int k = 0; k < 16; k++) {
            float e[4], f[4];
            #pragma unroll
            for (int r = 0; r < 4; r++) e[r] = Es[k][ty * 4 + r];
            #pragma unroll
            for (int c = 0; c < 4; c++) f[c] = Fs[k][tx * 4 + c];
            #pragma unroll
            for (int r = 0; r < 4; r++)
                #pragma unroll
                for (int c = 0; c < 4; c++) acc[r][c] += e[r] * f[c];
        }
        __syncthreads();
    }
    float* pb = part + (size_t)chunk * BATCH * CH * MPIX + (size_t)b * CH * MPIX;
    #pragma unroll
    for (int r = 0; r < 4; r++) {
        int j = j0 + ty * 4 + r;
        float inv = 1.f / css[ty * 4 + r];
        #pragma unroll
        for (int c = 0; c < 4; c++) {
            int d = tx * 4 + c;
            pb[(size_t)((d << 2) + h) * MPIX + j] = acc[r][c] * inv;
        }
    }
}

__global__ void mapo_reduce(const float* __restrict__ part, float* __restrict__ mapo) {
    int i = blockIdx.x * 256 + threadIdx.x;
    float s = 0.f;
    #pragma unroll
    for (int c = 0; c < KCHUNKS; c++)
        s += part[(size_t)c * BATCH * CH * MPIX + i];
    mapo[i] = s;
}

// ---------------- host launch ----------------
extern "C" void kernel_launch(void* const* d_in, const int* in_sizes, int n_in,
                              void* d_out, int out_size) {
    const float* feat = (const float*)d_in[0];
    const float* smap = (const float*)d_in[1];
    const float* Wfqv = (const float*)d_in[2];
    const float* Wmqv = (const float*)d_in[3];
    const float* Wfo  = (const float*)d_in[4];
    const float* Wmo  = (const float*)d_in[5];
    float* out = (float*)d_out;
    float* feat_out = out;
    float* map_out  = out + (size_t)BATCH * CH * NPIX;

    float *p_fqv, *p_mqv, *p_logits, *p_feato, *p_mapo, *p_part, *p_pm, *p_ps, *p_cm, *p_cs;
    cudaGetSymbolAddress((void**)&p_fqv, g_fqv);
    cudaGetSymbolAddress((void**)&p_mqv, g_mqv);
    cudaGetSymbolAddress((void**)&p_logits, g_logits);
    cudaGetSymbolAddress((void**)&p_feato, g_feato);
    cudaGetSymbolAddress((void**)&p_mapo, g_mapo);
    cudaGetSymbolAddress((void**)&p_part, g_mapo_part);
    cudaGetSymbolAddress((void**)&p_pm, g_pm);
    cudaGetSymbolAddress((void**)&p_ps, g_ps);
    cudaGetSymbolAddress((void**)&p_cm, g_cmax);
    cudaGetSymbolAddress((void**)&p_cs, g_csum);

    const int feato_smem = (64 * 257 + 64 * 65) * 4;  // 82432 B
    cudaFuncSetAttribute(feato_kernel, cudaFuncAttributeMaxDynamicSharedMemorySize, feato_smem);

    // 1) QV projections
    conv1x1_big<<<dim3(NPIX / 128, QVCH / 128, BATCH), 256>>>(Wfqv, feat, p_fqv, CH, NPIX, QVCH);
    conv1x1_small<<<dim3(MPIX / 64, QVCH / 64, BATCH), 256>>>(Wmqv, smap, p_mqv, CH, MPIX, QVCH);

    // 2) logits with fused column partial stats
    logits_big<<<dim3(MPIX / 128, NPIX / 128, NBH), 256>>>(p_fqv, p_mqv, p_logits, p_pm, p_ps);
    colstats_combine72<<<NBH, 256>>>(p_pm, p_ps, p_cm, p_cs);

    // 3) feat_o = rowsoftmax(logits) @ map_v
    feato_kernel<<<dim3(NPIX / 64, NBH), 256, feato_smem>>>(p_logits, p_mqv, p_feato);

    // 4) map_o = colsoftmax(logits)^T @ feat_v (split-K)
    mapo_kernel<<<dim3(MPIX / 64, KCHUNKS, NBH), 256>>>(p_logits, p_fqv, p_cm, p_cs, p_part);
    mapo_reduce<<<(BATCH * CH * MPIX) / 256, 256>>>(p_part, p_mapo);

    // 5) output projections
    conv1x1_big<<<dim3(NPIX / 128, CH / 128, BATCH), 256>>>(Wfo, p_feato, feat_out, CH, NPIX, CH);
    conv1x1_small<<<dim3(MPIX / 64, CH / 64, BATCH), 256>>>(Wmo, p_mapo, map_out, CH, MPIX, CH);
}

// round 4
// speedup vs baseline: 1.0039x; 1.0039x over previous
#include <cuda_runtime.h>
#include <cstdint>
#include <cstddef>

#define BATCH 4
#define CH    256
#define QVCH  512
#define NPIX  9216   // 96*96
#define MPIX  256    // 16*16
#define HEADS 4
#define DHEAD 64
#define NBH   (BATCH*HEADS)
#define KCHUNKS 16
#define ROWS_PER_CHUNK (NPIX/KCHUNKS)   // 576
#define IBLKS (NPIX/128)                // 72 logits i-blocks per bh
#define SCALE 0.125f

// ---------------- scratch (device globals; allocation-free) ----------------
__device__ float g_fqv[BATCH*QVCH*NPIX];
__device__ float g_mqv[BATCH*QVCH*MPIX];
__device__ float g_logits[(size_t)NBH*NPIX*MPIX];
__device__ float g_feato[BATCH*CH*NPIX];
__device__ float g_mapo[BATCH*CH*MPIX];
__device__ float g_mapo_part[KCHUNKS*BATCH*CH*MPIX];
__device__ float g_pm[NBH*IBLKS*MPIX];
__device__ float g_ps[NBH*IBLKS*MPIX];
__device__ float g_cmax[NBH*MPIX];
__device__ float g_csum[NBH*MPIX];

// =================== 128x128 tiled 1x1-conv GEMM ===================
// Y[b][o][n] = sum_c W[o][c]*X[b][c][n]; grid (Npix/128, O/128, BATCH), block 256
__global__ void __launch_bounds__(256, 2)
conv1x1_big(const float* __restrict__ Wm, const float* __restrict__ X,
            float* __restrict__ Y, int C, int Npix, int O) {
    __shared__ float As[8][132];   // [c][o]
    __shared__ float Bs[8][128];   // [c][n]
    int b = blockIdx.z;
    const float* Xb = X + (size_t)b * C * Npix;
    float* Yb = Y + (size_t)b * O * Npix;
    int o0 = blockIdx.y * 128, n0 = blockIdx.x * 128;
    int tid = threadIdx.x;
    int tx = tid & 15, ty = tid >> 4;

    // load mappings
    int oA = tid >> 1, cqA = (tid & 1) << 2;
    int cB = tid >> 5, nB = (tid & 31) << 2;
    const float* Wp = Wm + (size_t)(o0 + oA) * C + cqA;
    const float* Xp = Xb + (size_t)cB * Npix + n0 + nB;

    float acc[8][8] = {};
    float4 aw = *(const float4*)Wp;
    float4 bw = *(const float4*)Xp;

    for (int k0 = 0; k0 < C; k0 += 8) {
        As[cqA + 0][oA] = aw.x;
        As[cqA + 1][oA] = aw.y;
        As[cqA + 2][oA] = aw.z;
        As[cqA + 3][oA] = aw.w;
        *(float4*)&Bs[cB][nB] = bw;
        __syncthreads();
        if (k0 + 8 < C) {
            aw = *(const float4*)(Wp + k0 + 8);
            bw = *(const float4*)(Xp + (size_t)(k0 + 8) * Npix);
        }
        #pragma unroll
        for (int k = 0; k < 8; k++) {
            float a[8], bb[8];
            #pragma unroll
            for (int r = 0; r < 8; r++) a[r] = As[k][ty * 8 + r];
            #pragma unroll
            for (int c = 0; c < 8; c++) bb[c] = Bs[k][tx * 8 + c];
            #pragma unroll
            for (int r = 0; r < 8; r++)
                #pragma unroll
                for (int c = 0; c < 8; c++) acc[r][c] += a[r] * bb[c];
        }
        __syncthreads();
    }
    #pragma unroll
    for (int r = 0; r < 8; r++) {
        float* yrow = Yb + (size_t)(o0 + ty * 8 + r) * Npix + n0 + tx * 8;
        float4 v0 = make_float4(acc[r][0], acc[r][1], acc[r][2], acc[r][3]);
        float4 v1 = make_float4(acc[r][4], acc[r][5], acc[r][6], acc[r][7]);
        *(float4*)yrow = v0;
        *(float4*)(yrow + 4) = v1;
    }
}

// =================== small 64x64 conv (MPIX side) ===================
__global__ void conv1x1_small(const float* __restrict__ Wm,
                              const float* __restrict__ X,
                              float* __restrict__ Y,
                              int C, int Npix, int O) {
    __shared__ float As[16][65];
    __shared__ float Bs[16][64];
    int b = blockIdx.z;
    const float* Xb = X + (size_t)b * C * Npix;
    float* Yb = Y + (size_t)b * O * Npix;
    int o0 = blockIdx.y * 64, n0 = blockIdx.x * 64;
    int tid = threadIdx.x;
    int tx = tid & 15, ty = tid >> 4;
    float acc[4][4] = {};
    for (int k0 = 0; k0 < C; k0 += 16) {
        #pragma unroll
        for (int r = 0; r < 4; r++) {
            int idx = tid + r * 256;
            int c = idx & 15, o = idx >> 4;
            As[c][o] = Wm[(size_t)(o0 + o) * C + k0 + c];
        }
        #pragma unroll
        for (int r = 0; r < 4; r++) {
            int idx = tid + r * 256;
            int n = idx & 63, c = idx >> 6;
            Bs[c][n] = Xb[(size_t)(k0 + c) * Npix + n0 + n];
        }
        __syncthreads();
        #pragma unroll
        for (int k = 0; k < 16; k++) {
            float a[4], bb[4];
            #pragma unroll
            for (int r = 0; r < 4; r++) a[r] = As[k][ty * 4 + r];
            #pragma unroll
            for (int c2 = 0; c2 < 4; c2++) bb[c2] = Bs[k][tx * 4 + c2];
            #pragma unroll
            for (int r = 0; r < 4; r++)
                #pragma unroll
                for (int c2 = 0; c2 < 4; c2++) acc[r][c2] += a[r] * bb[c2];
        }
        __syncthreads();
    }
    #pragma unroll
    for (int r = 0; r < 4; r++)
        #pragma unroll
        for (int c2 = 0; c2 < 4; c2++)
            Yb[(size_t)(o0 + ty * 4 + r) * Npix + n0 + tx * 4 + c2] = acc[r][c2];
}

// =================== logits 128x128 + fused column partial stats ===================
// logits[bh][i][j] = SCALE * sum_d q[d][i]*k[d][j]; also per-block col max/sumexp
// grid (MPIX/128=2, NPIX/128=72, NBH), block 256
__global__ void __launch_bounds__(256, 2)
logits_big(const float* __restrict__ fqv, const float* __restrict__ mqv,
           float* __restrict__ logits, float* __restrict__ pm, float* __restrict__ ps) {
    __shared__ float Qs[8][128];   // [d][i]
    __shared__ float Ks[8][128];   // [d][j]
    __shared__ float red[16][128];
    int bh = blockIdx.z; int b = bh >> 2, h = bh & 3;
    int i0 = blockIdx.y * 128, j0 = blockIdx.x * 128;
    const float* qb = fqv + (size_t)b * QVCH * NPIX;
    const float* kb = mqv + (size_t)b * QVCH * MPIX;
    int tid = threadIdx.x;
    int tx = tid & 15, ty = tid >> 4;

    int dL = tid >> 5, e4 = (tid & 31) << 2;
    const float* qp = qb + (size_t)((dL << 2) + h) * NPIX + i0 + e4;
    const float* kp = kb + (size_t)((dL << 2) + h) * MPIX + j0 + e4;

    float acc[8][8] = {};
    float4 qw = *(const float4*)qp;
    float4 kw = *(const float4*)kp;

    for (int k0 = 0; k0 < DHEAD; k0 += 8) {
        *(float4*)&Qs[dL][e4] = qw;
        *(float4*)&Ks[dL][e4] = kw;
        __syncthreads();
        if (k0 + 8 < DHEAD) {
            qw = *(const float4*)(qp + (size_t)((k0 + 8) << 2) * NPIX);
            kw = *(const float4*)(kp + (size_t)((k0 + 8) << 2) * MPIX);
        }
        #pragma unroll
        for (int k = 0; k < 8; k++) {
            float a[8], bb[8];
            #pragma unroll
            for (int r = 0; r < 8; r++) a[r] = Qs[k][ty * 8 + r];
            #pragma unroll
            for (int c = 0; c < 8; c++) bb[c] = Ks[k][tx * 8 + c];
            #pragma unroll
            for (int r = 0; r < 8; r++)
                #pragma unroll
                for (int c = 0; c < 8; c++) acc[r][c] += a[r] * bb[c];
        }
        __syncthreads();
    }
    // scale + write logits
    float* lb = logits + (size_t)bh * NPIX * MPIX;
    #pragma unroll
    for (int r = 0; r < 8; r++) {
        #pragma unroll
        for (int c = 0; c < 8; c++) acc[r][c] *= SCALE;
        float* row = lb + (size_t)(i0 + ty * 8 + r) * MPIX + j0 + tx * 8;
        *(float4*)row = make_float4(acc[r][0], acc[r][1], acc[r][2], acc[r][3]);
        *(float4*)(row + 4) = make_float4(acc[r][4], acc[r][5], acc[r][6], acc[r][7]);
    }
    // fused column stats over this block's 128 rows
    float mloc[8];
    #pragma unroll
    for (int c = 0; c < 8; c++) {
        float m = acc[0][c];
        #pragma unroll
        for (int r = 1; r < 8; r++) m = fmaxf(m, acc[r][c]);
        mloc[c] = m;
    }
    #pragma unroll
    for (int c = 0; c < 8; c++) red[ty][tx * 8 + c] = mloc[c];
    __syncthreads();
    for (int s = 8; s > 0; s >>= 1) {
        if (ty < s) {
            #pragma unroll
            for (int c = 0; c < 8; c++)
                red[ty][tx * 8 + c] = fmaxf(red[ty][tx * 8 + c], red[ty + s][tx * 8 + c]);
        }
        __syncthreads();
    }
    float mcol[8];
    #pragma unroll
    for (int c = 0; c < 8; c++) mcol[c] = red[0][tx * 8 + c];
    __syncthreads();
    float sl[8];
    #pragma unroll
    for (int c = 0; c < 8; c++) {
        float s = 0.f;
        #pragma unroll
        for (int r = 0; r < 8; r++) s += __expf(acc[r][c] - mcol[c]);
        sl[c] = s;
    }
    #pragma unroll
    for (int c = 0; c < 8; c++) red[ty][tx * 8 + c] = sl[c];
    __syncthreads();
    for (int s = 8; s > 0; s >>= 1) {
        if (ty < s) {
            #pragma unroll
            for (int c = 0; c < 8; c++)
                red[ty][tx * 8 + c] += red[ty + s][tx * 8 + c];
        }
        __syncthreads();
    }
    if (ty == 0) {
        size_t base = ((size_t)bh * IBLKS + blockIdx.y) * MPIX + j0;
        #pragma unroll
        for (int c = 0; c < 8; c++) {
            pm[base + tx * 8 + c] = mcol[c];
            ps[base + tx * 8 + c] = red[0][tx * 8 + c];
        }
    }
}

// combine 72 i-block partials into column max/sum
__global__ void colstats_combine72(const float* __restrict__ pm,
                                   const float* __restrict__ ps,
                                   float* __restrict__ cm, float* __restrict__ cs) {
    int bh = blockIdx.x, j = threadIdx.x;
    float m = -1e30f;
    for (int c = 0; c < IBLKS; c++)
        m = fmaxf(m, pm[((size_t)bh * IBLKS + c) * MPIX + j]);
    float s = 0.f;
    for (int c = 0; c < IBLKS; c++)
        s += ps[((size_t)bh * IBLKS + c) * MPIX + j] *
             __expf(pm[((size_t)bh * IBLKS + c) * MPIX + j] - m);
    cm[bh * MPIX + j] = m;
    cs[bh * MPIX + j] = s;
}

// =================== feat_o: row softmax fused with P @ V (64x64 GEMM tiles) ===================
// grid (NPIX/64=144, NBH), block 256, dyn smem = 64*257*4 + 64*65*4
__global__ void __launch_bounds__(256, 2)
feato_kernel(const float* __restrict__ logits, const float* __restrict__ mqv,
             float* __restrict__ feato) {
    extern __shared__ float sm[];
    float* P = sm;              // [64][257]
    float* Vs = sm + 64 * 257;  // [64][65], reused as output staging
    int bh = blockIdx.y; int b = bh >> 2, h = bh & 3;
    int i0 = blockIdx.x * 64;
    const float* lb = logits + (size_t)bh * NPIX * MPIX;
    const float* vb = mqv + (size_t)b * QVCH * MPIX + (size_t)CH * MPIX;
    int tid = threadIdx.x, lane = tid & 31, warp = tid >> 5;
    int tx = tid & 15, ty = tid >> 4;

    // phase 1: softmax 8 rows per warp into P
    #pragma unroll
    for (int rr = 0; rr < 8; rr++) {
        int il = warp * 8 + rr;
        const float* row = lb + (size_t)(i0 + il) * MPIX;
        float x[8];
        float m = -1e30f;
        #pragma unroll
        for (int jj = 0; jj < 8; jj++) { x[jj] = row[jj * 32 + lane]; m = fmaxf(m, x[jj]); }
        #pragma unroll
        for (int off = 16; off; off >>= 1) m = fmaxf(m, __shfl_xor_sync(0xffffffffu, m, off));
        float s = 0.f;
        #pragma unroll
        for (int jj = 0; jj < 8; jj++) { x[jj] = __expf(x[jj] - m); s += x[jj]; }
        #pragma unroll
        for (int off = 16; off; off >>= 1) s += __shfl_xor_sync(0xffffffffu, s, off);
        float inv = 1.f / s;
        #pragma unroll
        for (int jj = 0; jj < 8; jj++) P[il * 257 + jj * 32 + lane] = x[jj] * inv;
    }
    __syncthreads();

    // phase 2: GEMM 64(i) x 64(d), K=256 in 4 chunks of 64
    float acc[4][4] = {};
    for (int kc = 0; kc < 4; kc++) {
        #pragma unroll
        for (int r = 0; r < 16; r++) {
            int idx = tid + r * 256;
            int k = idx & 63, d = idx >> 6;
            Vs[k * 65 + d] = vb[(size_t)((d << 2) + h) * MPIX + kc * 64 + k];
        }
        __syncthreads();
        #pragma unroll 4
        for (int k = 0; k < 64; k++) {
            float a[4], bb[4];
            #pragma unroll
            for (int r = 0; r < 4; r++) a[r] = P[(ty * 4 + r) * 257 + kc * 64 + k];
            #pragma unroll
            for (int c = 0; c < 4; c++) bb[c] = Vs[k * 65 + tx * 4 + c];
            #pragma unroll
            for (int r = 0; r < 4; r++)
                #pragma unroll
                for (int c = 0; c < 4; c++) acc[r][c] += a[r] * bb[c];
        }
        __syncthreads();
    }
    // stage output [i][d] then coalesced store
    #pragma unroll
    for (int r = 0; r < 4; r++)
        #pragma unroll
        for (int c = 0; c < 4; c++)
            Vs[(ty * 4 + r) * 65 + tx * 4 + c] = acc[r][c];
    __syncthreads();
    float* fb = feato + (size_t)b * CH * NPIX;
    #pragma unroll
    for (int r = 0; r < 16; r++) {
        int idx = tid + r * 256;
        int i = idx & 63, d = idx >> 6;
        fb[(size_t)((d << 2) + h) * NPIX + i0 + i] = Vs[i * 65 + d];
    }
}

// =================== map_o split-K partials ===================
__global__ void mapo_kernel(const float* __restrict__ logits,
                            const float* __restrict__ fqv,
                            const float* __restrict__ cm,
                            const float* __restrict__ cs,
                            float* __restrict__ part) {
    __shared__ float Es[16][64];
    __shared__ float Fs[16][65];
    __shared__ float cms[64], css[64];
    int bh = blockIdx.z; int b = bh >> 2, h = bh & 3;
    int j0 = blockIdx.x * 64;
    int chunk = blockIdx.y;
    int ibeg = chunk * ROWS_PER_CHUNK;
    const float* lb = logits + (size_t)bh * NPIX * MPIX;
    const float* fvb = fqv + (size_t)b * QVCH * NPIX + (size_t)CH * NPIX;
    int tid = threadIdx.x, tx = tid & 15, ty = tid >> 4;
    if (tid < 64) {
        cms[tid] = cm[bh * MPIX + j0 + tid];
        css[tid] = cs[bh * MPIX + j0 + tid];
    }
    __syncthreads();
    float acc[4][4] = {};
    for (int k0 = 0; k0 < ROWS_PER_CHUNK; k0 += 16) {
        int ib = ibeg + k0;
        #pragma unroll
        for (int r = 0; r < 4; r++) {
            int idx = tid + r * 256;
            int j = idx & 63, il = idx >> 6;
            float x = lb[(size_t)(ib + il) * MPIX + j0 + j];
            Es[il][j] = __expf(x - cms[j]);
        }
        #pragma unroll
        for (int r = 0; r < 4; r++) {
            int idx = tid + r * 256;
            int il = idx & 15, d = idx >> 4;
            Fs[il][d] = fvb[(size_t)((d << 2) + h) * NPIX + ib + il];
        }
        __syncthreads();
        #pragma unroll
        for (int k = 0; k < 16; k++) {
            float e[4], f[4];
            #pragma unroll
            for (int r = 0; r < 4; r++) e[r] = Es[k][ty * 4 + r];
            #pragma unroll
            for (int c = 0; c < 4; c++) f[c] = Fs[k][tx * 4 + c];
            #pragma unroll
            for (int r = 0; r < 4; r++)
                #pragma unroll
                for (int c = 0; c < 4; c++) acc[r][c] += e[r] * f[c];
        }
        __syncthreads();
    }
    float* pb = part + (size_t)chunk * BATCH * CH * MPIX + (size_t)b * CH * MPIX;
    #pragma unroll
    for (int r = 0; r < 4; r++) {
        int j = j0 + ty * 4 + r;
        float inv = 1.f / css[ty * 4 + r];
        #pragma unroll
        for (int c = 0; c < 4; c++) {
            int d = tx * 4 + c;
            pb[(size_t)((d << 2) + h) * MPIX + j] = acc[r][c] * inv;
        }
    }
}

__global__ void mapo_reduce(const float* __restrict__ part, float* __restrict__ mapo) {
    int i = blockIdx.x * 256 + threadIdx.x;
    float s = 0.f;
    #pragma unroll
    for (int c = 0; c < KCHUNKS; c++)
        s += part[(size_t)c * BATCH * CH * MPIX + i];
    mapo[i] = s;
}

// ---------------- host launch ----------------
extern "C" void kernel_launch(void* const* d_in, const int* in_sizes, int n_in,
                              void* d_out, int out_size) {
    const float* feat = (const float*)d_in[0];
    const float* smap = (const float*)d_in[1];
    const float* Wfqv = (const float*)d_in[2];
    const float* Wmqv = (const float*)d_in[3];
    const float* Wfo  = (const float*)d_in[4];
    const float* Wmo  = (const float*)d_in[5];
    float* out = (float*)d_out;
    float* feat_out = out;
    float* map_out  = out + (size_t)BATCH * CH * NPIX;

    float *p_fqv, *p_mqv, *p_logits, *p_feato, *p_mapo, *p_part, *p_pm, *p_ps, *p_cm, *p_cs;
    cudaGetSymbolAddress((void**)&p_fqv, g_fqv);
    cudaGetSymbolAddress((void**)&p_mqv, g_mqv);
    cudaGetSymbolAddress((void**)&p_logits, g_logits);
    cudaGetSymbolAddress((void**)&p_feato, g_feato);
    cudaGetSymbolAddress((void**)&p_mapo, g_mapo);
    cudaGetSymbolAddress((void**)&p_part, g_mapo_part);
    cudaGetSymbolAddress((void**)&p_pm, g_pm);
    cudaGetSymbolAddress((void**)&p_ps, g_ps);
    cudaGetSymbolAddress((void**)&p_cm, g_cmax);
    cudaGetSymbolAddress((void**)&p_cs, g_csum);

    const int feato_smem = (64 * 257 + 64 * 65) * 4;  // 82432 B
    cudaFuncSetAttribute(feato_kernel, cudaFuncAttributeMaxDynamicSharedMemorySize, feato_smem);

    // 1) QV projections
    conv1x1_big<<<dim3(NPIX / 128, QVCH / 128, BATCH), 256>>>(Wfqv, feat, p_fqv, CH, NPIX, QVCH);
    conv1x1_small<<<dim3(MPIX / 64, QVCH / 64, BATCH), 256>>>(Wmqv, smap, p_mqv, CH, MPIX, QVCH);

    // 2) logits with fused column partial stats
    logits_big<<<dim3(MPIX / 128, NPIX / 128, NBH), 256>>>(p_fqv, p_mqv, p_logits, p_pm, p_ps);
    colstats_combine72<<<NBH, 256>>>(p_pm, p_ps, p_cm, p_cs);

    // 3) feat_o = rowsoftmax(logits) @ map_v
    feato_kernel<<<dim3(NPIX / 64, NBH), 256, feato_smem>>>(p_logits, p_mqv, p_feato);

    // 4) map_o = colsoftmax(logits)^T @ feat_v (split-K)
    mapo_kernel<<<dim3(MPIX / 64, KCHUNKS, NBH), 256>>>(p_logits, p_fqv, p_cm, p_cs, p_part);
    mapo_reduce<<<(BATCH * CH * MPIX) / 256, 256>>>(p_part, p_mapo);

    // 5) output projections
    conv1x1_big<<<dim3(NPIX / 128, CH / 128, BATCH), 256>>>(Wfo, p_feato, feat_out, CH, NPIX, CH);
    conv1x1_small<<<dim3(MPIX / 64, CH / 64, BATCH), 256>>>(Wmo, p_mapo, map_out, CH, MPIX, CH);
}